// round 6
// baseline (speedup 1.0000x reference)
#include <cuda_runtime.h>
#include <cuda_bf16.h>

#define S 128
#define TSTR 132        // smem tile row stride (floats)
#define NCTA 148        // persistent: exactly one wave
#define NTILE 2048      // 16 * 128

__device__ __align__(16) unsigned g_mrow[16 * S * 4];  // bit j: mask[b,i,j]
__device__ __align__(16) unsigned g_span[16 * S * 4];  // bit k: mask[b,j,k] | mask[b,k,j]

__device__ __forceinline__ float sigmoidf_(float x) {
    return 1.0f / (1.0f + __expf(-x));
}
__device__ __forceinline__ unsigned smem_u32(const void* p) {
    unsigned r;
    asm("{ .reg .u64 t; cvta.to.shared.u64 t, %1; cvt.u32.u64 %0, t; }" : "=r"(r) : "l"(p));
    return r;
}
#define CP_ASYNC16(dst, src) \
    asm volatile("cp.async.cg.shared.global [%0], [%1], 16;\n" :: "r"(dst), "l"(src))
#define CP_COMMIT() asm volatile("cp.async.commit_group;\n")
#define CP_WAIT1()  asm volatile("cp.async.wait_group 1;\n")

__device__ __forceinline__ unsigned pick_word(uint4 v, int wd) {
    return (wd == 0) ? v.x : (wd == 1) ? v.y : (wd == 2) ? v.z : v.w;
}

// ---- Pre-kernel: pack masks to bits, one CTA per batch ----
__global__ __launch_bounds__(512)
void mask_pack_kernel(const int* __restrict__ mask) {
    __shared__ unsigned char m[S * TSTR];
    const int b = blockIdx.x;
    const int t = threadIdx.x;
    const int4* mg = reinterpret_cast<const int4*>(mask + (size_t)b * S * S);
    #pragma unroll
    for (int n = 0; n < 8; n++) {
        int idx = n * 512 + t;
        int row = idx >> 5, c4 = idx & 31;
        int4 v = __ldg(mg + idx);
        uchar4 u;
        u.x = (unsigned char)(v.x != 0); u.y = (unsigned char)(v.y != 0);
        u.z = (unsigned char)(v.z != 0); u.w = (unsigned char)(v.w != 0);
        *reinterpret_cast<uchar4*>(&m[row * TSTR + (c4 << 2)]) = u;
    }
    __syncthreads();
    const int w = t >> 5, lane = t & 31;
    for (int task = w; task < 512; task += 16) {
        const int j  = task >> 2;
        const int wd = task & 3;
        const int k  = (wd << 5) + lane;
        unsigned mjk = m[j * TSTR + k];
        unsigned mkj = m[k * TSTR + j];
        unsigned rw = __ballot_sync(0xffffffffu, mjk != 0);
        unsigned sw = __ballot_sync(0xffffffffu, (mjk | mkj) != 0);
        if (lane == 0) {
            g_mrow[(b * S + j) * 4 + wd] = rw;
            g_span[(b * S + j) * 4 + wd] = sw;
        }
    }
}

// ---- Main kernel: persistent CTAs, double-buffered cp.async pipeline ----
extern __shared__ float sm[];

__global__ __launch_bounds__(512, 1)
void mfvi_main(const float* __restrict__ s_span,
               const float* __restrict__ s_pair,
               float* __restrict__ out)
{
    float* p    = sm + 2 * S * TSTR;    // S
    float* part = p + S;                // 3*S

    const int t    = threadIdx.x;
    const int lane = t & 31;
    const int w    = t >> 5;            // 0..15
    const int j    = t & 127;
    const int h    = t >> 7;            // k-quarter 0..3
    const int kb   = h << 5;

    const unsigned bufb[2] = { smem_u32(sm), smem_u32(sm + S * TSTR) };
    const unsigned my_off  = (unsigned)(lane << 4);           // byte offset in a 512B row

    // --- prologue: issue loads for first tile into buffer 0 ---
    {
        const int n = blockIdx.x;
        const int b = n >> 7, i = n & 127;
        const uint4 mr = *reinterpret_cast<const uint4*>(&g_mrow[(b * S + i) * 4]);
        #pragma unroll
        for (int rr = 0; rr < 8; rr++) {
            const int r = (w << 3) + rr;
            if ((pick_word(mr, r >> 5) >> (r & 31)) & 1u)
                CP_ASYNC16(bufb[0] + (unsigned)(r * TSTR) * 4u + my_off,
                           s_pair + ((size_t)n * S + (size_t)r) * S + (lane << 2));
        }
        CP_COMMIT();
    }

    int cur = 0;
    for (int n = blockIdx.x; n < NTILE; n += NCTA, cur ^= 1) {
        // --- issue prefetch for next tile into the other buffer ---
        const int nn = n + NCTA;
        if (nn < NTILE) {
            const int b2 = nn >> 7, i2 = nn & 127;
            const uint4 mr2 = *reinterpret_cast<const uint4*>(&g_mrow[(b2 * S + i2) * 4]);
            #pragma unroll
            for (int rr = 0; rr < 8; rr++) {
                const int r = (w << 3) + rr;
                if ((pick_word(mr2, r >> 5) >> (r & 31)) & 1u)
                    CP_ASYNC16(bufb[cur ^ 1] + (unsigned)(r * TSTR) * 4u + my_off,
                               s_pair + ((size_t)nn * S + (size_t)r) * S + (lane << 2));
            }
        }
        CP_COMMIT();        // (possibly empty) keeps group counts aligned
        CP_WAIT1();         // current tile's data landed

        const int b = n >> 7, i = n & 127;
        const float* tile = (const float*)(cur ? (sm + S * TSTR) : sm);

        // per-tile scalars
        float ssj = 0.f;
        if (h == 0) {
            ssj = __ldg(&s_span[(size_t)n * S + j]);
            p[j] = sigmoidf_(ssj);              // p init (prev tile's p-reads all done)
        }
        const unsigned mij_w = __ldg(&g_mrow[(b * S + i) * 4 + (j >> 5)]);
        unsigned em = __ldg(&g_span[(b * S + j) * 4 + h]);
        if (!((mij_w >> (j & 31)) & 1u)) em = 0u;
        const int lo = min(i, j), hi = max(i, j);
        if ((lo >> 5) == h) em &= ~(1u << (lo & 31));
        if ((hi >> 5) == h) em &= ~(1u << (hi & 31));

        __syncthreads();    // tile data + p init visible

        // pull masked strip into registers
        float M[32];
        #pragma unroll
        for (int q = 0; q < 8; q++) {
            float4 v = *reinterpret_cast<const float4*>(&tile[j * TSTR + kb + (q << 2)]);
            M[4*q+0] = ((em >> (4*q+0)) & 1u) ? v.x : 0.f;
            M[4*q+1] = ((em >> (4*q+1)) & 1u) ? v.y : 0.f;
            M[4*q+2] = ((em >> (4*q+2)) & 1u) ? v.z : 0.f;
            M[4*q+3] = ((em >> (4*q+3)) & 1u) ? v.w : 0.f;
        }

        // 3 MFVI iterations
        #pragma unroll
        for (int it = 0; it < 3; it++) {
            float a0 = 0.f, a1 = 0.f, a2 = 0.f, a3 = 0.f;
            #pragma unroll
            for (int q = 0; q < 8; q++) {
                float4 pv = *reinterpret_cast<const float4*>(&p[kb + (q << 2)]);  // broadcast
                a0 = fmaf(pv.x, M[4*q+0], a0);
                a1 = fmaf(pv.y, M[4*q+1], a1);
                a2 = fmaf(pv.z, M[4*q+2], a2);
                a3 = fmaf(pv.w, M[4*q+3], a3);
            }
            float acc = (a0 + a1) + (a2 + a3);
            if (h) part[((h - 1) << 7) + j] = acc;
            __syncthreads();
            if (h == 0) {
                float qv = ssj + acc + part[j] + part[S + j] + part[2 * S + j];
                if (it < 2) p[j] = sigmoidf_(qv);
                else        out[(size_t)n * S + j] = sigmoidf_(qv);
            }
            if (it < 2) __syncthreads();
            else        __syncthreads();   // tile-final: guards p re-init + buffer reuse
        }
    }
}

extern "C" void kernel_launch(void* const* d_in, const int* in_sizes, int n_in,
                              void* d_out, int out_size) {
    const float* s_span = (const float*)d_in[0];
    const float* s_pair = (const float*)d_in[1];
    const int*   mask   = (const int*)d_in[2];
    float* out = (float*)d_out;

    const int smem_bytes = (2 * S * TSTR + 4 * S) * sizeof(float);  // ~137 KB
    cudaFuncSetAttribute(mfvi_main, cudaFuncAttributeMaxDynamicSharedMemorySize, smem_bytes);

    mask_pack_kernel<<<16, 512>>>(mask);
    mfvi_main<<<NCTA, 512, smem_bytes>>>(s_span, s_pair, out);
}

// round 7
// speedup vs baseline: 1.2538x; 1.2538x over previous
#include <cuda_runtime.h>
#include <cuda_bf16.h>

#define S 128
#define TSTR 132        // smem tile row stride (floats): conflict-free STS.128 + strided readback

__device__ __align__(16) unsigned g_mrow[16 * S * 4];  // bit j: mask[b,i,j]
__device__ __align__(16) unsigned g_span[16 * S * 4];  // bit k: mask[b,j,k] | mask[b,k,j]

__device__ __forceinline__ float sigmoidf_(float x) {
    return 1.0f / (1.0f + __expf(-x));
}
__device__ __forceinline__ unsigned smem_u32(const void* p) {
    unsigned r;
    asm("{ .reg .u64 t; cvta.to.shared.u64 t, %1; cvt.u32.u64 %0, t; }" : "=r"(r) : "l"(p));
    return r;
}
#define CP_ASYNC16(dst, src) \
    asm volatile("cp.async.cg.shared.global [%0], [%1], 16;\n" :: "r"(dst), "l"(src))
#define CP_COMMIT() asm volatile("cp.async.commit_group;\n")
#define CP_WAIT0()  asm volatile("cp.async.wait_group 0;\n")

__device__ __forceinline__ unsigned pick_word(uint4 v, int wd) {
    return (wd == 0) ? v.x : (wd == 1) ? v.y : (wd == 2) ? v.z : v.w;
}

// ---- Pre-kernel: pack masks to bits, one CTA per batch ----
__global__ __launch_bounds__(512)
void mask_pack_kernel(const int* __restrict__ mask) {
    __shared__ unsigned char m[S * TSTR];
    const int b = blockIdx.x;
    const int t = threadIdx.x;
    const int4* mg = reinterpret_cast<const int4*>(mask + (size_t)b * S * S);
    #pragma unroll
    for (int n = 0; n < 8; n++) {
        int idx = n * 512 + t;
        int row = idx >> 5, c4 = idx & 31;
        int4 v = __ldg(mg + idx);
        uchar4 u;
        u.x = (unsigned char)(v.x != 0); u.y = (unsigned char)(v.y != 0);
        u.z = (unsigned char)(v.z != 0); u.w = (unsigned char)(v.w != 0);
        *reinterpret_cast<uchar4*>(&m[row * TSTR + (c4 << 2)]) = u;
    }
    __syncthreads();
    const int w = t >> 5, lane = t & 31;
    for (int task = w; task < 512; task += 16) {
        const int j  = task >> 2;
        const int wd = task & 3;
        const int k  = (wd << 5) + lane;
        unsigned mjk = m[j * TSTR + k];
        unsigned mkj = m[k * TSTR + j];
        unsigned rw = __ballot_sync(0xffffffffu, mjk != 0);
        unsigned sw = __ballot_sync(0xffffffffu, (mjk | mkj) != 0);
        if (lane == 0) {
            g_mrow[(b * S + j) * 4 + wd] = rw;
            g_span[(b * S + j) * 4 + wd] = sw;
        }
    }
}

// ---- Main kernel: one CTA per (b,i), 256 threads, 2 independent CTAs/SM ----
extern __shared__ float sm[];

__global__ __launch_bounds__(256, 2)
void mfvi_main(const float* __restrict__ s_span,
               const float* __restrict__ s_pair,
               float* __restrict__ out)
{
    float* tile = sm;                // S * TSTR (~66 KB)
    float* p    = sm + S * TSTR;     // S
    float* part = p + S;             // S (h==1 partials)

    const int t    = threadIdx.x;
    const int lane = t & 31;
    const int w    = t >> 5;         // warp 0..7
    const int j    = t & 127;
    const int h    = t >> 7;         // k-half 0..1
    const int kb   = h << 6;

    const int n = blockIdx.x;        // (b,i) tile id
    const int b = n >> 7;
    const int i = n & 127;

    // ---- Issue ALL row loads immediately (predicated by mask row bits) ----
    const uint4 mr = *reinterpret_cast<const uint4*>(&g_mrow[(b * S + i) * 4]);
    {
        const unsigned tb = smem_u32(tile);
        const unsigned my_off = (unsigned)(lane << 4);
        #pragma unroll
        for (int rr = 0; rr < 16; rr++) {
            const int r = (w << 4) + rr;
            if ((pick_word(mr, r >> 5) >> (r & 31)) & 1u)
                CP_ASYNC16(tb + (unsigned)(r * TSTR) * 4u + my_off,
                           s_pair + ((size_t)n * S + (size_t)r) * S + (lane << 2));
        }
        CP_COMMIT();
    }

    // ---- Overlap with load: scalars, element-mask words, p init ----
    float ssj = 0.f;
    if (h == 0) {
        ssj = __ldg(&s_span[(size_t)n * S + j]);
        p[j] = sigmoidf_(ssj);
    }
    unsigned em0 = __ldg(&g_span[(b * S + j) * 4 + (h << 1) + 0]);
    unsigned em1 = __ldg(&g_span[(b * S + j) * 4 + (h << 1) + 1]);
    if (!((pick_word(mr, j >> 5) >> (j & 31)) & 1u)) { em0 = 0u; em1 = 0u; }
    {
        const int lo = min(i, j), hi = max(i, j);
        if ((lo >> 5) == ((kb) >> 5))      em0 &= ~(1u << (lo & 31));
        if ((lo >> 5) == ((kb + 32) >> 5)) em1 &= ~(1u << (lo & 31));
        if ((hi >> 5) == ((kb) >> 5))      em0 &= ~(1u << (hi & 31));
        if ((hi >> 5) == ((kb + 32) >> 5)) em1 &= ~(1u << (hi & 31));
    }

    CP_WAIT0();
    __syncthreads();   // tile + p init visible

    // ---- Pull masked 64-float strip into registers ----
    float M[64];
    #pragma unroll
    for (int q = 0; q < 16; q++) {
        float4 v = *reinterpret_cast<const float4*>(&tile[j * TSTR + kb + (q << 2)]);
        const unsigned em = (q < 8) ? em0 : em1;
        const int sh = (q << 2) & 31;
        M[4*q+0] = ((em >> (sh + 0)) & 1u) ? v.x : 0.f;
        M[4*q+1] = ((em >> (sh + 1)) & 1u) ? v.y : 0.f;
        M[4*q+2] = ((em >> (sh + 2)) & 1u) ? v.z : 0.f;
        M[4*q+3] = ((em >> (sh + 3)) & 1u) ? v.w : 0.f;
    }

    // ---- 3 MFVI iterations ----
    #pragma unroll
    for (int it = 0; it < 3; it++) {
        float a0 = 0.f, a1 = 0.f, a2 = 0.f, a3 = 0.f;
        #pragma unroll
        for (int q = 0; q < 16; q++) {
            float4 pv = *reinterpret_cast<const float4*>(&p[kb + (q << 2)]);  // broadcast
            a0 = fmaf(pv.x, M[4*q+0], a0);
            a1 = fmaf(pv.y, M[4*q+1], a1);
            a2 = fmaf(pv.z, M[4*q+2], a2);
            a3 = fmaf(pv.w, M[4*q+3], a3);
        }
        float acc = (a0 + a1) + (a2 + a3);
        if (h) part[j] = acc;
        __syncthreads();
        if (h == 0) {
            float qv = ssj + acc + part[j];
            if (it < 2) p[j] = sigmoidf_(qv);
            else        out[(size_t)n * S + j] = sigmoidf_(qv);
        }
        if (it < 2) __syncthreads();
    }
}

extern "C" void kernel_launch(void* const* d_in, const int* in_sizes, int n_in,
                              void* d_out, int out_size) {
    const float* s_span = (const float*)d_in[0];
    const float* s_pair = (const float*)d_in[1];
    const int*   mask   = (const int*)d_in[2];
    float* out = (float*)d_out;

    const int smem_bytes = (S * TSTR + 2 * S) * sizeof(float);  // ~68.6 KB
    cudaFuncSetAttribute(mfvi_main, cudaFuncAttributeMaxDynamicSharedMemorySize, smem_bytes);

    mask_pack_kernel<<<16, 512>>>(mask);
    mfvi_main<<<16 * 128, 256, smem_bytes>>>(s_span, s_pair, out);
}